// round 2
// baseline (speedup 1.0000x reference)
#include <cuda_runtime.h>
#include <math.h>

#define NN 55296      // nodes
#define NE 221184     // edges
#define BB 2
#define HH 32

// ---------------- device scratch (globals: allocation-free rule) ------------
__device__ float g_We[(size_t)NE * 1024];      // ~906 MB, per-edge 32x32 weight
__device__ float g_z[(size_t)NE * 32];         // edge hidden (relu(er@ew1+eb1))
__device__ float g_state[(size_t)BB * NN * HH];
__device__ float g_agg[(size_t)BB * NN * HH];

// ---------------- packed f32x2 helpers --------------------------------------
__device__ __forceinline__ unsigned long long pk2(float a, float b) {
    unsigned long long r;
    asm("mov.b64 %0, {%1, %2};" : "=l"(r) : "f"(a), "f"(b));
    return r;
}
__device__ __forceinline__ void fma2(unsigned long long& d,
                                     unsigned long long a,
                                     unsigned long long b) {
    asm("fma.rn.f32x2 %0, %1, %2, %3;" : "=l"(d) : "l"(a), "l"(b), "l"(d));
}
__device__ __forceinline__ float2 upk2(unsigned long long v) {
    float2 r;
    asm("mov.b64 {%0, %1}, %2;" : "=f"(r.x), "=f"(r.y) : "l"(v));
    return r;
}

// ---------------- 1. node projection: h0 = relu(x@pw1+pb1)@pw2+pb2 ----------
__global__ void proj_kernel(const float* __restrict__ x,
                            const float* __restrict__ pw1,
                            const float* __restrict__ pb1,
                            const float* __restrict__ pw2,
                            const float* __restrict__ pb2) {
    __shared__ float w1s[32][32], w2s[32][32], b1s[32], b2s[32];
    int tid = threadIdx.x;
    for (int i = tid; i < 1024; i += blockDim.x) {
        w1s[i >> 5][i & 31] = pw1[i];
        w2s[i >> 5][i & 31] = pw2[i];
    }
    if (tid < 32) { b1s[tid] = pb1[tid]; b2s[tid] = pb2[tid]; }
    __syncthreads();

    int lane = tid & 31;
    int row = blockIdx.x * (blockDim.x >> 5) + (tid >> 5);   // [0, BB*NN)
    if (row >= BB * NN) return;

    float xv = x[(size_t)row * 32 + lane];
    float t = b1s[lane];
    #pragma unroll
    for (int h = 0; h < 32; h++)
        t = fmaf(__shfl_sync(0xffffffffu, xv, h), w1s[h][lane], t);
    t = fmaxf(t, 0.0f);
    float o = b2s[lane];
    #pragma unroll
    for (int h = 0; h < 32; h++)
        o = fmaf(__shfl_sync(0xffffffffu, t, h), w2s[h][lane], o);
    g_state[(size_t)row * 32 + lane] = o;
}

// ---------------- 2. edge hidden: z = relu(er@ew1 + eb1) --------------------
__global__ void zed_kernel(const float* __restrict__ er,
                           const float* __restrict__ ew1,
                           const float* __restrict__ eb1) {
    int lane = threadIdx.x & 31;
    int e = blockIdx.x * (blockDim.x >> 5) + (threadIdx.x >> 5);
    if (e >= NE) return;
    float r0 = __ldg(er + (size_t)e * 4 + 0);
    float r1 = __ldg(er + (size_t)e * 4 + 1);
    float r2 = __ldg(er + (size_t)e * 4 + 2);
    float r3 = __ldg(er + (size_t)e * 4 + 3);
    float acc = __ldg(eb1 + lane);
    acc = fmaf(r0, __ldg(ew1 + 0 * 32 + lane), acc);
    acc = fmaf(r1, __ldg(ew1 + 1 * 32 + lane), acc);
    acc = fmaf(r2, __ldg(ew1 + 2 * 32 + lane), acc);
    acc = fmaf(r3, __ldg(ew1 + 3 * 32 + lane), acc);
    g_z[(size_t)e * 32 + lane] = fmaxf(acc, 0.0f);
}

// ---------------- 3. We GEMM: We[e, j] = z[e,:]@ew2[:,j] + eb2[j] -----------
// tile: 64 edges x 128 j, block 256, thread: 8 edges x 4 j (f32x2 packed)
__global__ void __launch_bounds__(256) we_kernel(const float* __restrict__ ew2,
                                                 const float* __restrict__ eb2) {
    __shared__ __align__(16) float zs[32][64];    // [k][e_local]
    __shared__ __align__(16) float ws[32][128];   // [k][j_local]
    int e0 = blockIdx.x * 64;
    int j0 = blockIdx.y * 128;
    int tid = threadIdx.x;

    for (int i = tid; i < 64 * 32; i += 256) {
        int el = i >> 5, k = i & 31;
        zs[k][el] = g_z[(size_t)(e0 + el) * 32 + k];
    }
    for (int i = tid; i < 32 * 128; i += 256) {
        int k = i >> 7, jl = i & 127;
        ws[k][jl] = ew2[(size_t)k * 1024 + j0 + jl];
    }
    __syncthreads();

    int tj = tid & 31;   // j group -> jl = tj*4
    int te = tid >> 5;   // e group -> el = te*8
    unsigned long long acc[8][2];
    #pragma unroll
    for (int i = 0; i < 8; i++) { acc[i][0] = 0ull; acc[i][1] = 0ull; }

    #pragma unroll 8
    for (int k = 0; k < 32; k++) {
        ulonglong2 w = *reinterpret_cast<const ulonglong2*>(&ws[k][tj * 4]);
        #pragma unroll
        for (int i = 0; i < 8; i++) {
            float zv = zs[k][te * 8 + i];
            unsigned long long zz = pk2(zv, zv);
            fma2(acc[i][0], zz, w.x);
            fma2(acc[i][1], zz, w.y);
        }
    }

    float4 bv = *reinterpret_cast<const float4*>(eb2 + j0 + tj * 4);
    #pragma unroll
    for (int i = 0; i < 8; i++) {
        float2 lo = upk2(acc[i][0]);
        float2 hi = upk2(acc[i][1]);
        float4 o = make_float4(lo.x + bv.x, lo.y + bv.y, hi.x + bv.z, hi.y + bv.w);
        *reinterpret_cast<float4*>(
            g_We + (size_t)(e0 + te * 8 + i) * 1024 + j0 + tj * 4) = o;
    }
}

// ---------------- 4. zero agg ------------------------------------------------
__global__ void zero_kernel() {
    size_t i = (size_t)blockIdx.x * blockDim.x + threadIdx.x;
    if (i < (size_t)BB * NN * HH) g_agg[i] = 0.0f;
}

// ---------------- 5. message + scatter: agg[b,dst] += node[b,src]@We[e] -----
__global__ void edge_kernel(const int* __restrict__ src,
                            const int* __restrict__ dst) {
    int lane = threadIdx.x & 31;
    int e = blockIdx.x * (blockDim.x >> 5) + (threadIdx.x >> 5);
    if (e >= NE) return;
    int s = __ldg(src + e);
    int d = __ldg(dst + e);

    float n0 = g_state[(size_t)s * 32 + lane];
    float n1 = g_state[(size_t)NN * 32 + (size_t)s * 32 + lane];
    const float* wrow = g_We + (size_t)e * 1024;

    float a0 = 0.0f, a1 = 0.0f;
    #pragma unroll
    for (int h = 0; h < 32; h++) {
        float w = wrow[h * 32 + lane];
        a0 = fmaf(__shfl_sync(0xffffffffu, n0, h), w, a0);
        a1 = fmaf(__shfl_sync(0xffffffffu, n1, h), w, a1);
    }
    atomicAdd(&g_agg[(size_t)d * 32 + lane], a0);
    atomicAdd(&g_agg[(size_t)NN * 32 + (size_t)d * 32 + lane], a1);
}

// ---------------- 6. relu+bias + GRU step (both batches per warp) -----------
__global__ void __launch_bounds__(256) gru_kernel(const float* __restrict__ conv_b,
                                                  const float* __restrict__ wih,
                                                  const float* __restrict__ whh,
                                                  const float* __restrict__ bih,
                                                  const float* __restrict__ bhh) {
    __shared__ float wihs[32][96];   // [h][j]  (transposed -> conflict-free)
    __shared__ float whhs[32][96];
    __shared__ float bihs[96], bhhs[96], cbs[32];
    int tid = threadIdx.x;
    for (int i = tid; i < 96 * 32; i += blockDim.x) {
        int j = i >> 5, h = i & 31;
        wihs[h][j] = wih[i];
        whhs[h][j] = whh[i];
    }
    if (tid < 96) { bihs[tid] = bih[tid]; bhhs[tid] = bhh[tid]; }
    if (tid < 32) cbs[tid] = conv_b[tid];
    __syncthreads();

    int lane = tid & 31;
    int n = blockIdx.x * (blockDim.x >> 5) + (tid >> 5);
    if (n >= NN) return;

    size_t i0 = (size_t)n * 32 + lane;
    size_t i1 = (size_t)NN * 32 + i0;
    float a0 = fmaxf(g_agg[i0] + cbs[lane], 0.0f);
    float a1 = fmaxf(g_agg[i1] + cbs[lane], 0.0f);
    float s0 = g_state[i0];
    float s1 = g_state[i1];

    float xr0 = bihs[lane],      xr1 = xr0;
    float xz0 = bihs[lane + 32], xz1 = xz0;
    float xn0 = bihs[lane + 64], xn1 = xn0;
    float hr0 = bhhs[lane],      hr1 = hr0;
    float hz0 = bhhs[lane + 32], hz1 = hz0;
    float hn0 = bhhs[lane + 64], hn1 = hn0;

    #pragma unroll
    for (int h = 0; h < 32; h++) {
        float wr = wihs[h][lane];
        float wz = wihs[h][lane + 32];
        float wn = wihs[h][lane + 64];
        float ur = whhs[h][lane];
        float uz = whhs[h][lane + 32];
        float un = whhs[h][lane + 64];
        float av0 = __shfl_sync(0xffffffffu, a0, h);
        float sv0 = __shfl_sync(0xffffffffu, s0, h);
        float av1 = __shfl_sync(0xffffffffu, a1, h);
        float sv1 = __shfl_sync(0xffffffffu, s1, h);
        xr0 = fmaf(av0, wr, xr0);  xz0 = fmaf(av0, wz, xz0);  xn0 = fmaf(av0, wn, xn0);
        hr0 = fmaf(sv0, ur, hr0);  hz0 = fmaf(sv0, uz, hz0);  hn0 = fmaf(sv0, un, hn0);
        xr1 = fmaf(av1, wr, xr1);  xz1 = fmaf(av1, wz, xz1);  xn1 = fmaf(av1, wn, xn1);
        hr1 = fmaf(sv1, ur, hr1);  hz1 = fmaf(sv1, uz, hz1);  hn1 = fmaf(sv1, un, hn1);
    }

    float r0 = 1.0f / (1.0f + __expf(-(xr0 + hr0)));
    float z0 = 1.0f / (1.0f + __expf(-(xz0 + hz0)));
    float nn0 = tanhf(xn0 + r0 * hn0);
    float r1 = 1.0f / (1.0f + __expf(-(xr1 + hr1)));
    float z1 = 1.0f / (1.0f + __expf(-(xz1 + hz1)));
    float nn1 = tanhf(xn1 + r1 * hn1);

    g_state[i0] = (1.0f - z0) * nn0 + z0 * s0;
    g_state[i1] = (1.0f - z1) * nn1 + z1 * s1;
}

// ---------------- 7. final copy to output -----------------------------------
__global__ void copy_out_kernel(float* __restrict__ out) {
    size_t i = (size_t)blockIdx.x * blockDim.x + threadIdx.x;
    if (i < (size_t)BB * NN * HH) out[i] = g_state[i];
}

// ---------------- launch -----------------------------------------------------
extern "C" void kernel_launch(void* const* d_in, const int* in_sizes, int n_in,
                              void* d_out, int out_size) {
    const float* x      = (const float*)d_in[0];
    const float* er     = (const float*)d_in[1];
    const float* pw1    = (const float*)d_in[2];
    const float* pb1    = (const float*)d_in[3];
    const float* pw2    = (const float*)d_in[4];
    const float* pb2    = (const float*)d_in[5];
    const float* ew1    = (const float*)d_in[6];
    const float* eb1    = (const float*)d_in[7];
    const float* ew2    = (const float*)d_in[8];
    const float* eb2    = (const float*)d_in[9];
    const float* conv_b = (const float*)d_in[10];
    const float* wih    = (const float*)d_in[11];
    const float* whh    = (const float*)d_in[12];
    const float* bih    = (const float*)d_in[13];
    const float* bhh    = (const float*)d_in[14];
    const int*   src    = (const int*)d_in[15];
    const int*   dst    = (const int*)d_in[16];
    float* out = (float*)d_out;

    const int TPB = 256;
    const int rows = BB * NN;                 // 110592
    proj_kernel<<<rows / 8, TPB>>>(x, pw1, pb1, pw2, pb2);
    zed_kernel<<<NE / 8, TPB>>>(er, ew1, eb1);
    dim3 wg(NE / 64, 8);
    we_kernel<<<wg, TPB>>>(ew2, eb2);

    int aggN = BB * NN * HH;                  // 3538944
    for (int step = 0; step < 3; step++) {
        zero_kernel<<<(aggN + TPB - 1) / TPB, TPB>>>();
        edge_kernel<<<NE / 8, TPB>>>(src, dst);
        gru_kernel<<<NN / 8, TPB>>>(conv_b, wih, whh, bih, bhh);
    }
    copy_out_kernel<<<(aggN + TPB - 1) / TPB, TPB>>>(out);
}

// round 4
// speedup vs baseline: 1.1205x; 1.1205x over previous
#include <cuda_runtime.h>
#include <cuda_bf16.h>
#include <math.h>

#define NN 55296      // nodes
#define NE 221184     // edges
#define BB 2
#define HH 32

// ---------------- device scratch (globals: allocation-free rule) ------------
__device__ __nv_bfloat16 g_We16[(size_t)NE * 1024];  // ~453 MB per-edge 32x32 W
__device__ float g_z[(size_t)NE * 32];               // edge hidden
__device__ float g_state[(size_t)BB * NN * HH];
__device__ float g_agg[(size_t)BB * NN * HH];

// ---------------- packed f32x2 helpers --------------------------------------
__device__ __forceinline__ unsigned long long pk2(float a, float b) {
    unsigned long long r;
    asm("mov.b64 %0, {%1, %2};" : "=l"(r) : "f"(a), "f"(b));
    return r;
}
__device__ __forceinline__ void fma2(unsigned long long& d,
                                     unsigned long long a,
                                     unsigned long long b) {
    asm("fma.rn.f32x2 %0, %1, %2, %3;" : "=l"(d) : "l"(a), "l"(b), "l"(d));
}
__device__ __forceinline__ float2 upk2(unsigned long long v) {
    float2 r;
    asm("mov.b64 {%0, %1}, %2;" : "=f"(r.x), "=f"(r.y) : "l"(v));
    return r;
}

// ---------------- 1. node projection: h0 = relu(x@pw1+pb1)@pw2+pb2 ----------
__global__ void proj_kernel(const float* __restrict__ x,
                            const float* __restrict__ pw1,
                            const float* __restrict__ pb1,
                            const float* __restrict__ pw2,
                            const float* __restrict__ pb2) {
    __shared__ float w1s[32][32], w2s[32][32], b1s[32], b2s[32];
    int tid = threadIdx.x;
    for (int i = tid; i < 1024; i += blockDim.x) {
        w1s[i >> 5][i & 31] = pw1[i];
        w2s[i >> 5][i & 31] = pw2[i];
    }
    if (tid < 32) { b1s[tid] = pb1[tid]; b2s[tid] = pb2[tid]; }
    __syncthreads();

    int lane = tid & 31;
    int row = blockIdx.x * (blockDim.x >> 5) + (tid >> 5);   // [0, BB*NN)
    if (row >= BB * NN) return;

    float xv = x[(size_t)row * 32 + lane];
    float t = b1s[lane];
    #pragma unroll
    for (int h = 0; h < 32; h++)
        t = fmaf(__shfl_sync(0xffffffffu, xv, h), w1s[h][lane], t);
    t = fmaxf(t, 0.0f);
    float o = b2s[lane];
    #pragma unroll
    for (int h = 0; h < 32; h++)
        o = fmaf(__shfl_sync(0xffffffffu, t, h), w2s[h][lane], o);
    g_state[(size_t)row * 32 + lane] = o;
}

// ---------------- 2. edge hidden: z = relu(er@ew1 + eb1) --------------------
__global__ void zed_kernel(const float* __restrict__ er,
                           const float* __restrict__ ew1,
                           const float* __restrict__ eb1) {
    int lane = threadIdx.x & 31;
    int e = blockIdx.x * (blockDim.x >> 5) + (threadIdx.x >> 5);
    if (e >= NE) return;
    float r0 = __ldg(er + (size_t)e * 4 + 0);
    float r1 = __ldg(er + (size_t)e * 4 + 1);
    float r2 = __ldg(er + (size_t)e * 4 + 2);
    float r3 = __ldg(er + (size_t)e * 4 + 3);
    float acc = __ldg(eb1 + lane);
    acc = fmaf(r0, __ldg(ew1 + 0 * 32 + lane), acc);
    acc = fmaf(r1, __ldg(ew1 + 1 * 32 + lane), acc);
    acc = fmaf(r2, __ldg(ew1 + 2 * 32 + lane), acc);
    acc = fmaf(r3, __ldg(ew1 + 3 * 32 + lane), acc);
    g_z[(size_t)e * 32 + lane] = fmaxf(acc, 0.0f);
}

// ---------------- 3. We GEMM: We[e, j] = z[e,:]@ew2[:,j] + eb2[j] (bf16 out)
// tile: 64 edges x 128 j, block 256, thread: 8 edges x 4 j (f32x2 packed)
__global__ void __launch_bounds__(256) we_kernel(const float* __restrict__ ew2,
                                                 const float* __restrict__ eb2) {
    __shared__ __align__(16) float zs[32][64];    // [k][e_local]
    __shared__ __align__(16) float ws[32][128];   // [k][j_local]
    int e0 = blockIdx.x * 64;
    int j0 = blockIdx.y * 128;
    int tid = threadIdx.x;

    for (int i = tid; i < 64 * 32; i += 256) {
        int el = i >> 5, k = i & 31;
        zs[k][el] = g_z[(size_t)(e0 + el) * 32 + k];
    }
    for (int i = tid; i < 32 * 128; i += 256) {
        int k = i >> 7, jl = i & 127;
        ws[k][jl] = ew2[(size_t)k * 1024 + j0 + jl];
    }
    __syncthreads();

    int tj = tid & 31;   // j group -> jl = tj*4
    int te = tid >> 5;   // e group -> el = te*8
    unsigned long long acc[8][2];
    #pragma unroll
    for (int i = 0; i < 8; i++) { acc[i][0] = 0ull; acc[i][1] = 0ull; }

    #pragma unroll 8
    for (int k = 0; k < 32; k++) {
        ulonglong2 w = *reinterpret_cast<const ulonglong2*>(&ws[k][tj * 4]);
        #pragma unroll
        for (int i = 0; i < 8; i++) {
            float zv = zs[k][te * 8 + i];
            unsigned long long zz = pk2(zv, zv);
            fma2(acc[i][0], zz, w.x);
            fma2(acc[i][1], zz, w.y);
        }
    }

    float4 bv = *reinterpret_cast<const float4*>(eb2 + j0 + tj * 4);
    #pragma unroll
    for (int i = 0; i < 8; i++) {
        float2 lo = upk2(acc[i][0]);
        float2 hi = upk2(acc[i][1]);
        __nv_bfloat162 p0 = __float22bfloat162_rn(make_float2(lo.x + bv.x, lo.y + bv.y));
        __nv_bfloat162 p1 = __float22bfloat162_rn(make_float2(hi.x + bv.z, hi.y + bv.w));
        uint2 packed;
        packed.x = *reinterpret_cast<unsigned int*>(&p0);
        packed.y = *reinterpret_cast<unsigned int*>(&p1);
        *reinterpret_cast<uint2*>(
            g_We16 + (size_t)(e0 + te * 8 + i) * 1024 + j0 + tj * 4) = packed;
    }
}

// ---------------- 4. init agg with conv bias --------------------------------
__global__ void init_agg_kernel(const float* __restrict__ conv_b) {
    __shared__ float cb[32];
    if (threadIdx.x < 32) cb[threadIdx.x] = conv_b[threadIdx.x];
    __syncthreads();
    size_t i = (size_t)blockIdx.x * blockDim.x + threadIdx.x;
    if (i < (size_t)BB * NN * HH) g_agg[i] = cb[threadIdx.x & 31];
}

// ---------------- 5. message + scatter: agg[b,dst] += node[b,src]@We[e] -----
__global__ void edge_kernel(const int* __restrict__ src,
                            const int* __restrict__ dst) {
    int lane = threadIdx.x & 31;
    int e = blockIdx.x * (blockDim.x >> 5) + (threadIdx.x >> 5);
    if (e >= NE) return;
    int s = __ldg(src + e);
    int d = __ldg(dst + e);

    float n0 = g_state[(size_t)s * 32 + lane];
    float n1 = g_state[(size_t)NN * 32 + (size_t)s * 32 + lane];
    const __nv_bfloat16* wrow = g_We16 + (size_t)e * 1024;

    float a0 = 0.0f, a1 = 0.0f;
    #pragma unroll
    for (int h = 0; h < 32; h++) {
        float w = __bfloat162float(__ldg(wrow + h * 32 + lane));
        a0 = fmaf(__shfl_sync(0xffffffffu, n0, h), w, a0);
        a1 = fmaf(__shfl_sync(0xffffffffu, n1, h), w, a1);
    }
    atomicAdd(&g_agg[(size_t)d * 32 + lane], a0);
    atomicAdd(&g_agg[(size_t)NN * 32 + (size_t)d * 32 + lane], a1);
}

// ---------------- 6. relu + GRU step (both batches per warp) ----------------
__global__ void __launch_bounds__(256) gru_kernel(const float* __restrict__ wih,
                                                  const float* __restrict__ whh,
                                                  const float* __restrict__ bih,
                                                  const float* __restrict__ bhh,
                                                  float* __restrict__ outp,
                                                  int to_out) {
    __shared__ float wihs[32][96];   // [h][j]  (transposed -> conflict-free)
    __shared__ float whhs[32][96];
    __shared__ float bihs[96], bhhs[96];
    int tid = threadIdx.x;
    for (int i = tid; i < 96 * 32; i += blockDim.x) {
        int j = i >> 5, h = i & 31;
        wihs[h][j] = wih[i];
        whhs[h][j] = whh[i];
    }
    if (tid < 96) { bihs[tid] = bih[tid]; bhhs[tid] = bhh[tid]; }
    __syncthreads();

    int lane = tid & 31;
    int n = blockIdx.x * (blockDim.x >> 5) + (tid >> 5);
    if (n >= NN) return;

    size_t i0 = (size_t)n * 32 + lane;
    size_t i1 = (size_t)NN * 32 + i0;
    float a0 = fmaxf(g_agg[i0], 0.0f);
    float a1 = fmaxf(g_agg[i1], 0.0f);
    float s0 = g_state[i0];
    float s1 = g_state[i1];

    float xr0 = bihs[lane],      xr1 = xr0;
    float xz0 = bihs[lane + 32], xz1 = xz0;
    float xn0 = bihs[lane + 64], xn1 = xn0;
    float hr0 = bhhs[lane],      hr1 = hr0;
    float hz0 = bhhs[lane + 32], hz1 = hz0;
    float hn0 = bhhs[lane + 64], hn1 = hn0;

    #pragma unroll
    for (int h = 0; h < 32; h++) {
        float wr = wihs[h][lane];
        float wz = wihs[h][lane + 32];
        float wn = wihs[h][lane + 64];
        float ur = whhs[h][lane];
        float uz = whhs[h][lane + 32];
        float un = whhs[h][lane + 64];
        float av0 = __shfl_sync(0xffffffffu, a0, h);
        float sv0 = __shfl_sync(0xffffffffu, s0, h);
        float av1 = __shfl_sync(0xffffffffu, a1, h);
        float sv1 = __shfl_sync(0xffffffffu, s1, h);
        xr0 = fmaf(av0, wr, xr0);  xz0 = fmaf(av0, wz, xz0);  xn0 = fmaf(av0, wn, xn0);
        hr0 = fmaf(sv0, ur, hr0);  hz0 = fmaf(sv0, uz, hz0);  hn0 = fmaf(sv0, un, hn0);
        xr1 = fmaf(av1, wr, xr1);  xz1 = fmaf(av1, wz, xz1);  xn1 = fmaf(av1, wn, xn1);
        hr1 = fmaf(sv1, ur, hr1);  hz1 = fmaf(sv1, uz, hz1);  hn1 = fmaf(sv1, un, hn1);
    }

    float r0 = 1.0f / (1.0f + __expf(-(xr0 + hr0)));
    float z0 = 1.0f / (1.0f + __expf(-(xz0 + hz0)));
    float nn0 = tanhf(xn0 + r0 * hn0);
    float r1 = 1.0f / (1.0f + __expf(-(xr1 + hr1)));
    float z1 = 1.0f / (1.0f + __expf(-(xz1 + hz1)));
    float nn1 = tanhf(xn1 + r1 * hn1);

    float o0 = (1.0f - z0) * nn0 + z0 * s0;
    float o1 = (1.0f - z1) * nn1 + z1 * s1;
    // state always updated (next step reads it); final step also writes d_out
    g_state[i0] = o0;
    g_state[i1] = o1;
    if (to_out) {
        outp[i0] = o0;
        outp[i1] = o1;
    }
}

// ---------------- launch -----------------------------------------------------
extern "C" void kernel_launch(void* const* d_in, const int* in_sizes, int n_in,
                              void* d_out, int out_size) {
    const float* x      = (const float*)d_in[0];
    const float* er     = (const float*)d_in[1];
    const float* pw1    = (const float*)d_in[2];
    const float* pb1    = (const float*)d_in[3];
    const float* pw2    = (const float*)d_in[4];
    const float* pb2    = (const float*)d_in[5];
    const float* ew1    = (const float*)d_in[6];
    const float* eb1    = (const float*)d_in[7];
    const float* ew2    = (const float*)d_in[8];
    const float* eb2    = (const float*)d_in[9];
    const float* conv_b = (const float*)d_in[10];
    const float* wih    = (const float*)d_in[11];
    const float* whh    = (const float*)d_in[12];
    const float* bih    = (const float*)d_in[13];
    const float* bhh    = (const float*)d_in[14];
    const int*   src    = (const int*)d_in[15];
    const int*   dst    = (const int*)d_in[16];
    float* out = (float*)d_out;

    const int TPB = 256;
    const int rows = BB * NN;                 // 110592
    proj_kernel<<<rows / 8, TPB>>>(x, pw1, pb1, pw2, pb2);
    zed_kernel<<<NE / 8, TPB>>>(er, ew1, eb1);
    dim3 wg(NE / 64, 8);
    we_kernel<<<wg, TPB>>>(ew2, eb2);

    int aggN = BB * NN * HH;                  // 3538944
    for (int step = 0; step < 3; step++) {
        init_agg_kernel<<<(aggN + TPB - 1) / TPB, TPB>>>(conv_b);
        edge_kernel<<<NE / 8, TPB>>>(src, dst);
        gru_kernel<<<NN / 8, TPB>>>(wih, whh, bih, bhh, out, step == 2 ? 1 : 0);
    }
}

// round 5
// speedup vs baseline: 1.2057x; 1.0760x over previous
#include <cuda_runtime.h>
#include <cuda_bf16.h>
#include <math.h>

#define NN 55296      // nodes
#define NE 221184     // edges
#define BB 2
#define HH 32

// ---------------- device scratch (globals: allocation-free rule) ------------
__device__ __nv_bfloat16 g_We16[(size_t)NE * 1024];  // ~453 MB per-edge 32x32 W
__device__ float g_state[(size_t)BB * NN * HH];
__device__ float g_agg[(size_t)BB * NN * HH];

// ---------------- packed f32x2 helpers --------------------------------------
__device__ __forceinline__ unsigned long long pk2(float a, float b) {
    unsigned long long r;
    asm("mov.b64 %0, {%1, %2};" : "=l"(r) : "f"(a), "f"(b));
    return r;
}
__device__ __forceinline__ void fma2(unsigned long long& d,
                                     unsigned long long a,
                                     unsigned long long b) {
    asm("fma.rn.f32x2 %0, %1, %2, %3;" : "=l"(d) : "l"(a), "l"(b), "l"(d));
}
__device__ __forceinline__ float2 upk2(unsigned long long v) {
    float2 r;
    asm("mov.b64 {%0, %1}, %2;" : "=f"(r.x), "=f"(r.y) : "l"(v));
    return r;
}

// ---------------- 1. node projection: h0 = relu(x@pw1+pb1)@pw2+pb2 ----------
__global__ void proj_kernel(const float* __restrict__ x,
                            const float* __restrict__ pw1,
                            const float* __restrict__ pb1,
                            const float* __restrict__ pw2,
                            const float* __restrict__ pb2) {
    __shared__ float w1s[32][32], w2s[32][32], b1s[32], b2s[32];
    int tid = threadIdx.x;
    for (int i = tid; i < 1024; i += blockDim.x) {
        w1s[i >> 5][i & 31] = pw1[i];
        w2s[i >> 5][i & 31] = pw2[i];
    }
    if (tid < 32) { b1s[tid] = pb1[tid]; b2s[tid] = pb2[tid]; }
    __syncthreads();

    int lane = tid & 31;
    int row = blockIdx.x * (blockDim.x >> 5) + (tid >> 5);   // [0, BB*NN)
    if (row >= BB * NN) return;

    float xv = x[(size_t)row * 32 + lane];
    float t = b1s[lane];
    #pragma unroll
    for (int h = 0; h < 32; h++)
        t = fmaf(__shfl_sync(0xffffffffu, xv, h), w1s[h][lane], t);
    t = fmaxf(t, 0.0f);
    float o = b2s[lane];
    #pragma unroll
    for (int h = 0; h < 32; h++)
        o = fmaf(__shfl_sync(0xffffffffu, t, h), w2s[h][lane], o);
    g_state[(size_t)row * 32 + lane] = o;
}

// ---------------- 2. init agg with conv bias --------------------------------
__global__ void init_agg_kernel(const float* __restrict__ conv_b) {
    __shared__ float cb[32];
    if (threadIdx.x < 32) cb[threadIdx.x] = conv_b[threadIdx.x];
    __syncthreads();
    size_t i = (size_t)blockIdx.x * blockDim.x + threadIdx.x;
    if (i < (size_t)BB * NN * HH) g_agg[i] = cb[threadIdx.x & 31];
}

// ---------------- 3. We GEMM (z fused): We = relu(er@ew1+eb1)@ew2+eb2 (bf16)
// tile: 64 edges x 128 j, block 256, thread: 8 edges x 4 j (f32x2 packed)
__global__ void __launch_bounds__(256) we_kernel(const float* __restrict__ er,
                                                 const float* __restrict__ ew1,
                                                 const float* __restrict__ eb1,
                                                 const float* __restrict__ ew2,
                                                 const float* __restrict__ eb2) {
    __shared__ __align__(16) float zs[32][64];    // [k][e_local]
    __shared__ __align__(16) float ws[32][128];   // [k][j_local]
    int e0 = blockIdx.x * 64;
    int j0 = blockIdx.y * 128;
    int tid = threadIdx.x;

    // fused z computation: z[el][k] = relu(eb1[k] + er[e0+el] . ew1[:,k])
    {
        int k = tid & 31;
        float w0 = __ldg(ew1 + k);
        float w1 = __ldg(ew1 + 32 + k);
        float w2 = __ldg(ew1 + 64 + k);
        float w3 = __ldg(ew1 + 96 + k);
        float b  = __ldg(eb1 + k);
        #pragma unroll
        for (int it = 0; it < 8; it++) {
            int el = (tid >> 5) + 8 * it;
            float4 r = *reinterpret_cast<const float4*>(er + (size_t)(e0 + el) * 4);
            float z = b;
            z = fmaf(r.x, w0, z); z = fmaf(r.y, w1, z);
            z = fmaf(r.z, w2, z); z = fmaf(r.w, w3, z);
            zs[k][el] = fmaxf(z, 0.0f);
        }
    }
    for (int i = tid; i < 32 * 128; i += 256) {
        int k = i >> 7, jl = i & 127;
        ws[k][jl] = ew2[(size_t)k * 1024 + j0 + jl];
    }
    __syncthreads();

    int tj = tid & 31;   // j group -> jl = tj*4
    int te = tid >> 5;   // e group -> el = te*8
    unsigned long long acc[8][2];
    #pragma unroll
    for (int i = 0; i < 8; i++) { acc[i][0] = 0ull; acc[i][1] = 0ull; }

    #pragma unroll 8
    for (int k = 0; k < 32; k++) {
        ulonglong2 w = *reinterpret_cast<const ulonglong2*>(&ws[k][tj * 4]);
        #pragma unroll
        for (int i = 0; i < 8; i++) {
            float zv = zs[k][te * 8 + i];
            unsigned long long zz = pk2(zv, zv);
            fma2(acc[i][0], zz, w.x);
            fma2(acc[i][1], zz, w.y);
        }
    }

    float4 bv = *reinterpret_cast<const float4*>(eb2 + j0 + tj * 4);
    #pragma unroll
    for (int i = 0; i < 8; i++) {
        float2 lo = upk2(acc[i][0]);
        float2 hi = upk2(acc[i][1]);
        __nv_bfloat162 p0 = __float22bfloat162_rn(make_float2(lo.x + bv.x, lo.y + bv.y));
        __nv_bfloat162 p1 = __float22bfloat162_rn(make_float2(hi.x + bv.z, hi.y + bv.w));
        uint2 packed;
        packed.x = *reinterpret_cast<unsigned int*>(&p0);
        packed.y = *reinterpret_cast<unsigned int*>(&p1);
        *reinterpret_cast<uint2*>(
            g_We16 + (size_t)(e0 + te * 8 + i) * 1024 + j0 + tj * 4) = packed;
    }
}

// ---------------- 4. message + scatter: agg[b,dst] += node[b,src]@We[e] -----
// warp per edge; node pair staged in smem, packed f32x2 math, no shfl.
__global__ void __launch_bounds__(256) edge_kernel(const int* __restrict__ src,
                                                   const int* __restrict__ dst) {
    __shared__ __align__(8) float nvec[8][32][2];   // [warp][h][batch]
    int lane = threadIdx.x & 31;
    int w = threadIdx.x >> 5;
    int e = blockIdx.x * 8 + w;                     // NE % 8 == 0
    int s = __ldg(src + e);
    int d = __ldg(dst + e);

    nvec[w][lane][0] = g_state[(size_t)s * 32 + lane];
    nvec[w][lane][1] = g_state[(size_t)NN * 32 + (size_t)s * 32 + lane];
    __syncwarp();

    const unsigned short* wrow =
        reinterpret_cast<const unsigned short*>(g_We16 + (size_t)e * 1024);
    unsigned long long acc = 0ull;
    #pragma unroll
    for (int h = 0; h < 32; h++) {
        unsigned int wb = (unsigned int)__ldg(wrow + h * 32 + lane);
        float wf = __uint_as_float(wb << 16);
        unsigned long long wp = pk2(wf, wf);
        unsigned long long np =
            *reinterpret_cast<const unsigned long long*>(&nvec[w][h][0]);
        fma2(acc, np, wp);
    }
    float2 a = upk2(acc);
    atomicAdd(&g_agg[(size_t)d * 32 + lane], a.x);
    atomicAdd(&g_agg[(size_t)NN * 32 + (size_t)d * 32 + lane], a.y);
}

// ---------------- 5. relu + GRU step (both batches packed per warp) ---------
__global__ void __launch_bounds__(256) gru_kernel(const float* __restrict__ wih,
                                                  const float* __restrict__ whh,
                                                  const float* __restrict__ bih,
                                                  const float* __restrict__ bhh,
                                                  float* __restrict__ outp,
                                                  int to_out) {
    __shared__ float wihs[32][96];   // [h][j]  (transposed -> conflict-free)
    __shared__ float whhs[32][96];
    __shared__ float bihs[96], bhhs[96];
    __shared__ __align__(8) float avs[8][32][2];
    __shared__ __align__(8) float svs[8][32][2];
    int tid = threadIdx.x;
    for (int i = tid; i < 96 * 32; i += blockDim.x) {
        int j = i >> 5, h = i & 31;
        wihs[h][j] = wih[i];
        whhs[h][j] = whh[i];
    }
    if (tid < 96) { bihs[tid] = bih[tid]; bhhs[tid] = bhh[tid]; }
    __syncthreads();

    int lane = tid & 31;
    int w = tid >> 5;
    int n = blockIdx.x * 8 + w;                     // NN % 8 == 0

    size_t i0 = (size_t)n * 32 + lane;
    size_t i1 = (size_t)NN * 32 + i0;
    float a0 = fmaxf(g_agg[i0], 0.0f);
    float a1 = fmaxf(g_agg[i1], 0.0f);
    float s0 = g_state[i0];
    float s1 = g_state[i1];
    avs[w][lane][0] = a0;  avs[w][lane][1] = a1;
    svs[w][lane][0] = s0;  svs[w][lane][1] = s1;
    __syncwarp();

    unsigned long long xr = pk2(bihs[lane],      bihs[lane]);
    unsigned long long xz = pk2(bihs[lane + 32], bihs[lane + 32]);
    unsigned long long xn = pk2(bihs[lane + 64], bihs[lane + 64]);
    unsigned long long hr = pk2(bhhs[lane],      bhhs[lane]);
    unsigned long long hz = pk2(bhhs[lane + 32], bhhs[lane + 32]);
    unsigned long long hn = pk2(bhhs[lane + 64], bhhs[lane + 64]);

    #pragma unroll
    for (int h = 0; h < 32; h++) {
        unsigned long long av =
            *reinterpret_cast<const unsigned long long*>(&avs[w][h][0]);
        unsigned long long sv =
            *reinterpret_cast<const unsigned long long*>(&svs[w][h][0]);
        float wr = wihs[h][lane];
        float wz = wihs[h][lane + 32];
        float wn = wihs[h][lane + 64];
        float ur = whhs[h][lane];
        float uz = whhs[h][lane + 32];
        float un = whhs[h][lane + 64];
        fma2(xr, av, pk2(wr, wr));
        fma2(xz, av, pk2(wz, wz));
        fma2(xn, av, pk2(wn, wn));
        fma2(hr, sv, pk2(ur, ur));
        fma2(hz, sv, pk2(uz, uz));
        fma2(hn, sv, pk2(un, un));
    }

    float2 fxr = upk2(xr), fxz = upk2(xz), fxn = upk2(xn);
    float2 fhr = upk2(hr), fhz = upk2(hz), fhn = upk2(hn);

    float r0 = 1.0f / (1.0f + __expf(-(fxr.x + fhr.x)));
    float z0 = 1.0f / (1.0f + __expf(-(fxz.x + fhz.x)));
    float nn0 = tanhf(fxn.x + r0 * fhn.x);
    float r1 = 1.0f / (1.0f + __expf(-(fxr.y + fhr.y)));
    float z1 = 1.0f / (1.0f + __expf(-(fxz.y + fhz.y)));
    float nn1 = tanhf(fxn.y + r1 * fhn.y);

    float o0 = (1.0f - z0) * nn0 + z0 * s0;
    float o1 = (1.0f - z1) * nn1 + z1 * s1;
    g_state[i0] = o0;
    g_state[i1] = o1;
    if (to_out) {
        outp[i0] = o0;
        outp[i1] = o1;
    }
}

// ---------------- launch -----------------------------------------------------
extern "C" void kernel_launch(void* const* d_in, const int* in_sizes, int n_in,
                              void* d_out, int out_size) {
    const float* x      = (const float*)d_in[0];
    const float* er     = (const float*)d_in[1];
    const float* pw1    = (const float*)d_in[2];
    const float* pb1    = (const float*)d_in[3];
    const float* pw2    = (const float*)d_in[4];
    const float* pb2    = (const float*)d_in[5];
    const float* ew1    = (const float*)d_in[6];
    const float* eb1    = (const float*)d_in[7];
    const float* ew2    = (const float*)d_in[8];
    const float* eb2    = (const float*)d_in[9];
    const float* conv_b = (const float*)d_in[10];
    const float* wih    = (const float*)d_in[11];
    const float* whh    = (const float*)d_in[12];
    const float* bih    = (const float*)d_in[13];
    const float* bhh    = (const float*)d_in[14];
    const int*   src    = (const int*)d_in[15];
    const int*   dst    = (const int*)d_in[16];
    float* out = (float*)d_out;

    const int TPB = 256;
    const int rows = BB * NN;                 // 110592
    int aggN = BB * NN * HH;                  // 3538944

    // order chosen so edge_kernel is the 4th launch (ncu -s 5 -c 1 lands there)
    proj_kernel<<<rows / 8, TPB>>>(x, pw1, pb1, pw2, pb2);            // 1
    init_agg_kernel<<<(aggN + TPB - 1) / TPB, TPB>>>(conv_b);         // 2
    dim3 wg(NE / 64, 8);
    we_kernel<<<wg, TPB>>>(er, ew1, eb1, ew2, eb2);                   // 3

    for (int step = 0; step < 3; step++) {
        if (step > 0)
            init_agg_kernel<<<(aggN + TPB - 1) / TPB, TPB>>>(conv_b);
        edge_kernel<<<NE / 8, TPB>>>(src, dst);                       // 4 (step 0)
        gru_kernel<<<NN / 8, TPB>>>(wih, whh, bih, bhh, out, step == 2 ? 1 : 0);
    }
}

// round 7
// speedup vs baseline: 1.4983x; 1.2426x over previous
#include <cuda_runtime.h>
#include <cuda_bf16.h>
#include <math.h>
#include <stdint.h>

#define NN 55296      // nodes
#define NE 221184     // edges
#define BB 2
#define HH 32

#define E_TILE 128
#define J_TILE 512
#define WS_STRIDE 520   // bf16 elems per k-row (padded: banks k*4 mod 32, conflict-free)
#define ZS_STRIDE 40    // bf16 elems per e-row (padded: banks r*20 mod 32, conflict-free)

// ---------------- device scratch (globals: allocation-free rule) ------------
__device__ __nv_bfloat16 g_We16[(size_t)NE * 1024];  // ~453 MB per-edge 32x32 W
__device__ float g_state[(size_t)BB * NN * HH];
__device__ float g_agg[(size_t)BB * NN * HH];
__device__ float g_dummy[32];

// ---------------- helpers ----------------------------------------------------
__device__ __forceinline__ unsigned long long pk2(float a, float b) {
    unsigned long long r;
    asm("mov.b64 %0, {%1, %2};" : "=l"(r) : "f"(a), "f"(b));
    return r;
}
__device__ __forceinline__ void fma2(unsigned long long& d,
                                     unsigned long long a,
                                     unsigned long long b) {
    asm("fma.rn.f32x2 %0, %1, %2, %3;" : "=l"(d) : "l"(a), "l"(b), "l"(d));
}
__device__ __forceinline__ float2 upk2(unsigned long long v) {
    float2 r;
    asm("mov.b64 {%0, %1}, %2;" : "=f"(r.x), "=f"(r.y) : "l"(v));
    return r;
}
__device__ __forceinline__ uint32_t s2u(const void* p) {
    uint32_t a;
    asm("{ .reg .u64 t; cvta.to.shared.u64 t, %1; cvt.u32.u64 %0, t; }"
        : "=r"(a) : "l"(p));
    return a;
}

// ---------------- 0. profiling filler (shifts we_kernel to ncu slot 4) ------
__global__ void filler_kernel() {
    if (threadIdx.x < 32) g_dummy[threadIdx.x] = 0.0f;
}

// ---------------- 1. node projection: h0 = relu(x@pw1+pb1)@pw2+pb2 ----------
__global__ void proj_kernel(const float* __restrict__ x,
                            const float* __restrict__ pw1,
                            const float* __restrict__ pb1,
                            const float* __restrict__ pw2,
                            const float* __restrict__ pb2) {
    __shared__ float w1s[32][32], w2s[32][32], b1s[32], b2s[32];
    int tid = threadIdx.x;
    for (int i = tid; i < 1024; i += blockDim.x) {
        w1s[i >> 5][i & 31] = pw1[i];
        w2s[i >> 5][i & 31] = pw2[i];
    }
    if (tid < 32) { b1s[tid] = pb1[tid]; b2s[tid] = pb2[tid]; }
    __syncthreads();

    int lane = tid & 31;
    int row = blockIdx.x * (blockDim.x >> 5) + (tid >> 5);   // [0, BB*NN)
    if (row >= BB * NN) return;

    float xv = x[(size_t)row * 32 + lane];
    float t = b1s[lane];
    #pragma unroll
    for (int h = 0; h < 32; h++)
        t = fmaf(__shfl_sync(0xffffffffu, xv, h), w1s[h][lane], t);
    t = fmaxf(t, 0.0f);
    float o = b2s[lane];
    #pragma unroll
    for (int h = 0; h < 32; h++)
        o = fmaf(__shfl_sync(0xffffffffu, t, h), w2s[h][lane], o);
    g_state[(size_t)row * 32 + lane] = o;
}

// ---------------- 2. init agg with conv bias --------------------------------
__global__ void init_agg_kernel(const float* __restrict__ conv_b) {
    __shared__ float cb[32];
    if (threadIdx.x < 32) cb[threadIdx.x] = conv_b[threadIdx.x];
    __syncthreads();
    size_t i = (size_t)blockIdx.x * blockDim.x + threadIdx.x;
    if (i < (size_t)BB * NN * HH) g_agg[i] = cb[threadIdx.x & 31];
}

// ---------------- 3. We GEMM via tensor cores (mma.sync bf16) ---------------
// We[e, j] = relu(er@ew1+eb1)[e,:] @ ew2[:, j] + eb2[j], output bf16.
// tile: 128 e x 512 j per block; warp = 16 e x 512 j (64 n-tiles x 2 k-halves)
__global__ void __launch_bounds__(256) we_kernel(const float* __restrict__ er,
                                                 const float* __restrict__ ew1,
                                                 const float* __restrict__ eb1,
                                                 const float* __restrict__ ew2,
                                                 const float* __restrict__ eb2) {
    __shared__ __align__(16) __nv_bfloat16 ws[32 * WS_STRIDE];     // 33280 B
    __shared__ __align__(16) __nv_bfloat16 zs[E_TILE * ZS_STRIDE]; // 10240 B
    __shared__ float ebs[J_TILE];                                   // 2048 B
    __shared__ float ew1s[128], eb1s[32];

    int tid = threadIdx.x;
    int e0 = blockIdx.x * E_TILE;
    int j0 = blockIdx.y * J_TILE;

    if (tid < 128) ew1s[tid] = ew1[tid];
    else if (tid < 160) eb1s[tid - 128] = eb1[tid - 128];
    // stage ew2 chunk as bf16 [k][j] with padded stride
    for (int i = tid; i < 32 * J_TILE / 2; i += 256) {
        int flat = i * 2;
        int k = flat / J_TILE, j = flat % J_TILE;
        float2 v = *reinterpret_cast<const float2*>(ew2 + (size_t)k * 1024 + j0 + j);
        __nv_bfloat162 b = __float22bfloat162_rn(v);
        *reinterpret_cast<uint32_t*>(&ws[k * WS_STRIDE + j]) =
            *reinterpret_cast<uint32_t*>(&b);
    }
    for (int i = tid; i < J_TILE; i += 256) ebs[i] = eb2[j0 + i];
    __syncthreads();

    // z = relu(er@ew1 + eb1), bf16 into zs
    if (tid < 128) {
        int r = tid;
        float4 rv = *reinterpret_cast<const float4*>(er + (size_t)(e0 + r) * 4);
        #pragma unroll
        for (int kk = 0; kk < 16; kk++) {
            int ka = 2 * kk, kb = 2 * kk + 1;
            float za = eb1s[ka], zb = eb1s[kb];
            za = fmaf(rv.x, ew1s[ka], za);       zb = fmaf(rv.x, ew1s[kb], zb);
            za = fmaf(rv.y, ew1s[32 + ka], za);  zb = fmaf(rv.y, ew1s[32 + kb], zb);
            za = fmaf(rv.z, ew1s[64 + ka], za);  zb = fmaf(rv.z, ew1s[64 + kb], zb);
            za = fmaf(rv.w, ew1s[96 + ka], za);  zb = fmaf(rv.w, ew1s[96 + kb], zb);
            __nv_bfloat162 p = __floats2bfloat162_rn(fmaxf(za, 0.0f), fmaxf(zb, 0.0f));
            *reinterpret_cast<uint32_t*>(&zs[r * ZS_STRIDE + ka]) =
                *reinterpret_cast<uint32_t*>(&p);
        }
    }
    __syncthreads();

    int w = tid >> 5, lane = tid & 31;
    int grp = lane >> 2, qid = lane & 3;

    // A fragments: 16x32 per warp, loaded once (2 x ldmatrix.x4)
    uint32_t a[2][4];
    {
        int rsel = lane & 15;
        int csel8 = (lane >= 16) ? 8 : 0;
        uint32_t base = s2u(zs);
        #pragma unroll
        for (int kh = 0; kh < 2; kh++) {
            uint32_t addr = base +
                (uint32_t)(((w * 16 + rsel) * ZS_STRIDE + kh * 16 + csel8) * 2);
            asm volatile(
                "ldmatrix.sync.aligned.m8n8.x4.shared.b16 {%0,%1,%2,%3}, [%4];"
                : "=r"(a[kh][0]), "=r"(a[kh][1]), "=r"(a[kh][2]), "=r"(a[kh][3])
                : "r"(addr));
        }
    }

    uint32_t wsbase = s2u(ws);
    int eg0 = e0 + w * 16 + grp;
    int brow = lane & 15;

    for (int nt = 0; nt < J_TILE / 8; nt++) {
        int n0 = nt * 8;
        float d0 = 0.f, d1 = 0.f, d2 = 0.f, d3 = 0.f;
        #pragma unroll
        for (int kh = 0; kh < 2; kh++) {
            uint32_t baddr = wsbase +
                (uint32_t)(((kh * 16 + brow) * WS_STRIDE + n0) * 2);
            uint32_t b0, b1;
            asm volatile(
                "ldmatrix.sync.aligned.m8n8.x2.trans.shared.b16 {%0,%1}, [%2];"
                : "=r"(b0), "=r"(b1) : "r"(baddr));
            asm volatile(
                "mma.sync.aligned.m16n8k16.row.col.f32.bf16.bf16.f32 "
                "{%0,%1,%2,%3},{%4,%5,%6,%7},{%8,%9},{%0,%1,%2,%3};"
                : "+f"(d0), "+f"(d1), "+f"(d2), "+f"(d3)
                : "r"(a[kh][0]), "r"(a[kh][1]), "r"(a[kh][2]), "r"(a[kh][3]),
                  "r"(b0), "r"(b1));
        }
        float2 bv = *reinterpret_cast<const float2*>(&ebs[n0 + 2 * qid]);
        __nv_bfloat162 p0 = __float22bfloat162_rn(make_float2(d0 + bv.x, d1 + bv.y));
        __nv_bfloat162 p1 = __float22bfloat162_rn(make_float2(d2 + bv.x, d3 + bv.y));
        int j = j0 + n0 + 2 * qid;
        *reinterpret_cast<uint32_t*>(g_We16 + (size_t)eg0 * 1024 + j) =
            *reinterpret_cast<uint32_t*>(&p0);
        *reinterpret_cast<uint32_t*>(g_We16 + (size_t)(eg0 + 8) * 1024 + j) =
            *reinterpret_cast<uint32_t*>(&p1);
    }
}

// ---------------- 4. message + scatter: agg[b,dst] += node[b,src]@We[e] -----
__global__ void __launch_bounds__(256) edge_kernel(const int* __restrict__ src,
                                                   const int* __restrict__ dst) {
    __shared__ __align__(8) float nvec[8][32][2];   // [warp][h][batch]
    int lane = threadIdx.x & 31;
    int w = threadIdx.x >> 5;
    int e = blockIdx.x * 8 + w;                     // NE % 8 == 0
    int s = __ldg(src + e);
    int d = __ldg(dst + e);

    nvec[w][lane][0] = g_state[(size_t)s * 32 + lane];
    nvec[w][lane][1] = g_state[(size_t)NN * 32 + (size_t)s * 32 + lane];
    __syncwarp();

    const unsigned short* wrow =
        reinterpret_cast<const unsigned short*>(g_We16 + (size_t)e * 1024);
    unsigned long long acc = 0ull;
    #pragma unroll
    for (int h = 0; h < 32; h++) {
        unsigned int wb = (unsigned int)__ldg(wrow + h * 32 + lane);
        float wf = __uint_as_float(wb << 16);
        unsigned long long wp = pk2(wf, wf);
        unsigned long long np =
            *reinterpret_cast<const unsigned long long*>(&nvec[w][h][0]);
        fma2(acc, np, wp);
    }
    float2 a = upk2(acc);
    atomicAdd(&g_agg[(size_t)d * 32 + lane], a.x);
    atomicAdd(&g_agg[(size_t)NN * 32 + (size_t)d * 32 + lane], a.y);
}

// ---------------- 5. relu + GRU step (both batches packed per warp) ---------
__global__ void __launch_bounds__(256) gru_kernel(const float* __restrict__ wih,
                                                  const float* __restrict__ whh,
                                                  const float* __restrict__ bih,
                                                  const float* __restrict__ bhh,
                                                  float* __restrict__ outp,
                                                  int to_out) {
    __shared__ float wihs[32][96];   // [h][j]  (transposed -> conflict-free)
    __shared__ float whhs[32][96];
    __shared__ float bihs[96], bhhs[96];
    __shared__ __align__(8) float avs[8][32][2];
    __shared__ __align__(8) float svs[8][32][2];
    int tid = threadIdx.x;
    for (int i = tid; i < 96 * 32; i += blockDim.x) {
        int j = i >> 5, h = i & 31;
        wihs[h][j] = wih[i];
        whhs[h][j] = whh[i];
    }
    if (tid < 96) { bihs[tid] = bih[tid]; bhhs[tid] = bhh[tid]; }
    __syncthreads();

    int lane = tid & 31;
    int w = tid >> 5;
    int n = blockIdx.x * 8 + w;                     // NN % 8 == 0

    size_t i0 = (size_t)n * 32 + lane;
    size_t i1 = (size_t)NN * 32 + i0;
    float a0 = fmaxf(g_agg[i0], 0.0f);
    float a1 = fmaxf(g_agg[i1], 0.0f);
    float s0 = g_state[i0];
    float s1 = g_state[i1];
    avs[w][lane][0] = a0;  avs[w][lane][1] = a1;
    svs[w][lane][0] = s0;  svs[w][lane][1] = s1;
    __syncwarp();

    unsigned long long xr = pk2(bihs[lane],      bihs[lane]);
    unsigned long long xz = pk2(bihs[lane + 32], bihs[lane + 32]);
    unsigned long long xn = pk2(bihs[lane + 64], bihs[lane + 64]);
    unsigned long long hr = pk2(bhhs[lane],      bhhs[lane]);
    unsigned long long hz = pk2(bhhs[lane + 32], bhhs[lane + 32]);
    unsigned long long hn = pk2(bhhs[lane + 64], bhhs[lane + 64]);

    #pragma unroll
    for (int h = 0; h < 32; h++) {
        unsigned long long av =
            *reinterpret_cast<const unsigned long long*>(&avs[w][h][0]);
        unsigned long long sv =
            *reinterpret_cast<const unsigned long long*>(&svs[w][h][0]);
        float wr = wihs[h][lane];
        float wz = wihs[h][lane + 32];
        float wn = wihs[h][lane + 64];
        float ur = whhs[h][lane];
        float uz = whhs[h][lane + 32];
        float un = whhs[h][lane + 64];
        fma2(xr, av, pk2(wr, wr));
        fma2(xz, av, pk2(wz, wz));
        fma2(xn, av, pk2(wn, wn));
        fma2(hr, sv, pk2(ur, ur));
        fma2(hz, sv, pk2(uz, uz));
        fma2(hn, sv, pk2(un, un));
    }

    float2 fxr = upk2(xr), fxz = upk2(xz), fxn = upk2(xn);
    float2 fhr = upk2(hr), fhz = upk2(hz), fhn = upk2(hn);

    float r0 = 1.0f / (1.0f + __expf(-(fxr.x + fhr.x)));
    float z0 = 1.0f / (1.0f + __expf(-(fxz.x + fhz.x)));
    float nn0 = tanhf(fxn.x + r0 * fhn.x);
    float r1 = 1.0f / (1.0f + __expf(-(fxr.y + fhr.y)));
    float z1 = 1.0f / (1.0f + __expf(-(fxz.y + fhz.y)));
    float nn1 = tanhf(fxn.y + r1 * fhn.y);

    float o0 = (1.0f - z0) * nn0 + z0 * s0;
    float o1 = (1.0f - z1) * nn1 + z1 * s1;
    g_state[i0] = o0;
    g_state[i1] = o1;
    if (to_out) {
        outp[i0] = o0;
        outp[i1] = o1;
    }
}

// ---------------- launch -----------------------------------------------------
extern "C" void kernel_launch(void* const* d_in, const int* in_sizes, int n_in,
                              void* d_out, int out_size) {
    const float* x      = (const float*)d_in[0];
    const float* er     = (const float*)d_in[1];
    const float* pw1    = (const float*)d_in[2];
    const float* pb1    = (const float*)d_in[3];
    const float* pw2    = (const float*)d_in[4];
    const float* pb2    = (const float*)d_in[5];
    const float* ew1    = (const float*)d_in[6];
    const float* eb1    = (const float*)d_in[7];
    const float* ew2    = (const float*)d_in[8];
    const float* eb2    = (const float*)d_in[9];
    const float* conv_b = (const float*)d_in[10];
    const float* wih    = (const float*)d_in[11];
    const float* whh    = (const float*)d_in[12];
    const float* bih    = (const float*)d_in[13];
    const float* bhh    = (const float*)d_in[14];
    const int*   src    = (const int*)d_in[15];
    const int*   dst    = (const int*)d_in[16];
    float* out = (float*)d_out;

    const int TPB = 256;
    const int rows = BB * NN;                 // 110592
    int aggN = BB * NN * HH;                  // 3538944

    // slot 4 = we_kernel (ncu profiles the 4th launch)
    filler_kernel<<<1, 32>>>();                                       // 1
    proj_kernel<<<rows / 8, TPB>>>(x, pw1, pb1, pw2, pb2);            // 2
    init_agg_kernel<<<(aggN + TPB - 1) / TPB, TPB>>>(conv_b);         // 3
    dim3 wg(NE / E_TILE, 1024 / J_TILE);                              // (1728, 2)
    we_kernel<<<wg, TPB>>>(er, ew1, eb1, ew2, eb2);                   // 4

    for (int step = 0; step < 3; step++) {
        edge_kernel<<<NE / 8, TPB>>>(src, dst);
        gru_kernel<<<NN / 8, TPB>>>(wih, whh, bih, bhh, out, step == 2 ? 1 : 0);
        if (step < 2)
            init_agg_kernel<<<(aggN + TPB - 1) / TPB, TPB>>>(conv_b);
    }
}